// round 16
// baseline (speedup 1.0000x reference)
#include <cuda_runtime.h>
#include <math.h>

// Problem constants (fixed by the dataset)
#define N_NODES 100000
#define N_EDGES 1600000
#define NF      64
#define NC      40
#define CAP     64      // per-node slots; max degree ~38 (1.6M-into-100K multinomial)
#define GRP     16      // nodes per fused-kernel iteration (100000 % 16 == 0)

// Scratch: __device__ globals. float4-typed arrays are 16B-aligned.
// Referenced ONLY from device code (host-side &global is the R10 bug).
__device__ float4 g_h1_4[N_NODES * NF / 4];   // hidden after layer 1
__device__ float4 g_h2_4[N_NODES * NF / 4];   // hidden after layer 2
__device__ int    g_cnt [N_NODES];            // per-dst message count
__device__ int    g_slot[N_NODES * CAP];      // per-dst source-node lists
__device__ int    g_ei_is64;                  // 1 if edge_index is int64

// ---------------------------------------------------------------------------
// Zero per-node counters; thread 0 probes edge_index dtype (int64 ids < 2^31
// -> every odd 32-bit word zero; random int32 ids in [0,1e5) never are).
// ---------------------------------------------------------------------------
__global__ void zero_probe_kernel(const int* __restrict__ ei32) {
    int i = blockIdx.x * blockDim.x + threadIdx.x;
    if (i < N_NODES) g_cnt[i] = 0;
    if (i == 0) {
        int allzero = 1;
        for (int k = 1; k < 128; k += 2)
            if (ei32[k] != 0) { allzero = 0; break; }
        g_ei_is64 = allzero;
    }
}

// ---------------------------------------------------------------------------
// Build per-dst source lists ONCE (used by both layers). Ticketed atomicAdd
// into distinct addresses (~16 avg contention). Slot order is race-dependent;
// summation is commutative, verified by tolerance.
// ---------------------------------------------------------------------------
__global__ void build_kernel(const void* __restrict__ ei_raw) {
    int e = blockIdx.x * blockDim.x + threadIdx.x;
    if (e >= N_EDGES) return;
    int src, dst;
    if (g_ei_is64) {
        const long long* ei = (const long long*)ei_raw;
        src = (int)ei[e];
        dst = (int)ei[N_EDGES + e];
    } else {
        const int* ei = (const int*)ei_raw;
        src = ei[e];
        dst = ei[N_EDGES + e];
    }
    if ((unsigned)src >= N_NODES || (unsigned)dst >= N_NODES) return;
    int t = atomicAdd(&g_cnt[dst], 1);
    if (t < CAP) g_slot[dst * CAP + t] = src;
}

// ---------------------------------------------------------------------------
// Gather one float4 chunk of (h[n] + sum_{s in list(n)} h[s]).
// Unroll x4 -> 4 outstanding L2 gathers hide latency.
// ---------------------------------------------------------------------------
__device__ __forceinline__ float4 gather_row(const float4* __restrict__ h4,
                                             int n, int c) {
    float4 acc = h4[n * 16 + c];               // self-term (GIN eps=0)
    int deg = g_cnt[n];
    if (deg > CAP) deg = CAP;
    const int* sl = g_slot + n * CAP;
    int d = 0;
    for (; d + 4 <= deg; d += 4) {
        int s0 = sl[d], s1 = sl[d + 1], s2 = sl[d + 2], s3 = sl[d + 3];
        float4 v0 = h4[s0 * 16 + c];
        float4 v1 = h4[s1 * 16 + c];
        float4 v2 = h4[s2 * 16 + c];
        float4 v3 = h4[s3 * 16 + c];
        acc.x += (v0.x + v1.x) + (v2.x + v3.x);
        acc.y += (v0.y + v1.y) + (v2.y + v3.y);
        acc.z += (v0.z + v1.z) + (v2.z + v3.z);
        acc.w += (v0.w + v1.w) + (v2.w + v3.w);
    }
    for (; d < deg; d++) {
        float4 v = h4[sl[d] * 16 + c];
        acc.x += v.x; acc.y += v.y; acc.z += v.z; acc.w += v.w;
    }
    return acc;
}

// ---------------------------------------------------------------------------
// FUSED GIN layer: out = relu((h + sum msgs) @ W + b), no g_agg round-trip.
// 256 threads, 16 nodes/iteration, double-buffered smem, ONE barrier/iter:
//   per iter: STS(gathered regs -> buf p) ; BAR ; issue gather of group g+grid
//   (latency overlaps compute) ; 256-FMA compute on buf p.
// Race-free: a warp's STS to buf p at iter i+2 is ordered after all reads of
// buf p at iter i by the barrier at i+1.
// Gather role: 16 thr/node, coalesced 256B rows. Compute role: thread (nl,j)
// does column j of nodes nl+{0,4,8,12}: 16 indep FMA chains, w reused 4x,
// LDS.128 broadcast (whole warp same address).
// layer1 != 0: input x, output g_h1; else input g_h1, output g_h2.
// ---------------------------------------------------------------------------
__global__ void __launch_bounds__(256, 2)
fused_layer_kernel(const float4* __restrict__ xin,
                   const float* __restrict__ W,
                   const float* __restrict__ b,
                   int layer1) {
    __shared__ __align__(16) float tin[2][GRP * NF];
    const float4* h4  = layer1 ? xin : g_h1_4;
    float*        out = layer1 ? (float*)g_h1_4 : (float*)g_h2_4;

    int t  = threadIdx.x;
    int gn = t >> 4, gc = t & 15;     // gather role: node-in-group, chunk
    int nl = t >> 6, j  = t & 63;     // compute role: node base, column

    float w[NF];
#pragma unroll
    for (int k = 0; k < NF; k++) w[k] = W[k * NF + j];
    float bias = b[j];

    const int ngroups = N_NODES / GRP;        // 6250
    int g = blockIdx.x;
    float4 gacc = gather_row(h4, g * GRP + gn, gc);   // prologue gather
    int p = 0;

    for (; g < ngroups; g += gridDim.x) {
        *(float4*)&tin[p][gn * NF + gc * 4] = gacc;   // publish group g
        __syncthreads();

        int g2 = g + gridDim.x;                       // gather next group:
        if (g2 < ngroups)                             // loads in flight while
            gacc = gather_row(h4, g2 * GRP + gn, gc); // we compute below

#pragma unroll
        for (int m = 0; m < 4; m++) {
            const float* row = &tin[p][(nl + 4 * m) * NF];
            float a0 = bias, a1 = 0.f, a2 = 0.f, a3 = 0.f;
#pragma unroll
            for (int k = 0; k < NF / 4; k++) {
                float4 v = *(const float4*)(row + 4 * k);
                a0 = fmaf(v.x, w[4 * k],     a0);
                a1 = fmaf(v.y, w[4 * k + 1], a1);
                a2 = fmaf(v.z, w[4 * k + 2], a2);
                a3 = fmaf(v.w, w[4 * k + 3], a3);
            }
            out[(g * GRP + nl + 4 * m) * NF + j] = fmaxf((a0 + a1) + (a2 + a3), 0.f);
        }
        p ^= 1;
    }
}

// ---------------------------------------------------------------------------
// Classifier: logits = h2 @ Wf + bf (64 -> 40), per-row log_softmax.
// One warp per node; Wf/bf in smem; LDS.128 h-row; prefetch; shuffles; MUFU.
// Lane j owns classes j and j+32 (latter for j < 8).
// ---------------------------------------------------------------------------
__global__ void classifier_kernel(const float* __restrict__ Wf,
                                  const float* __restrict__ bf,
                                  float* __restrict__ out) {
    __shared__ float Wfs[NF * NC];
    __shared__ float bfs[NC];
    __shared__ __align__(16) float hrow[8][NF];

    const float* h2 = (const float*)g_h2_4;
    int t = threadIdx.x;
    for (int i = t; i < NF * NC; i += blockDim.x) Wfs[i] = Wf[i];
    if (t < NC) bfs[t] = bf[t];
    __syncthreads();

    int w    = t >> 5;
    int lane = t & 31;
    int warps_total = gridDim.x * (blockDim.x >> 5);
    int wg   = blockIdx.x * (blockDim.x >> 5) + w;
    bool has2 = lane < (NC - 32);

    int n = wg;
    float p0 = 0.f, p1 = 0.f;
    if (n < N_NODES) { p0 = h2[n * NF + lane]; p1 = h2[n * NF + 32 + lane]; }

    for (; n < N_NODES; n += warps_total) {
        hrow[w][lane]      = p0;
        hrow[w][lane + 32] = p1;
        __syncwarp();

        int nn = n + warps_total;
        if (nn < N_NODES) {
            p0 = h2[nn * NF + lane];
            p1 = h2[nn * NF + 32 + lane];
        }

        float acc0 = bfs[lane];
        float acc1 = has2 ? bfs[lane + 32] : 0.f;
#pragma unroll
        for (int k = 0; k < NF / 4; k++) {
            float4 hv = *(const float4*)&hrow[w][4 * k];
            acc0 = fmaf(hv.x, Wfs[(4 * k)     * NC + lane], acc0);
            acc0 = fmaf(hv.y, Wfs[(4 * k + 1) * NC + lane], acc0);
            acc0 = fmaf(hv.z, Wfs[(4 * k + 2) * NC + lane], acc0);
            acc0 = fmaf(hv.w, Wfs[(4 * k + 3) * NC + lane], acc0);
            if (has2) {
                acc1 = fmaf(hv.x, Wfs[(4 * k)     * NC + lane + 32], acc1);
                acc1 = fmaf(hv.y, Wfs[(4 * k + 1) * NC + lane + 32], acc1);
                acc1 = fmaf(hv.z, Wfs[(4 * k + 2) * NC + lane + 32], acc1);
                acc1 = fmaf(hv.w, Wfs[(4 * k + 3) * NC + lane + 32], acc1);
            }
        }

        float m = has2 ? fmaxf(acc0, acc1) : acc0;
#pragma unroll
        for (int o = 16; o; o >>= 1)
            m = fmaxf(m, __shfl_xor_sync(0xffffffffu, m, o));

        float s = __expf(acc0 - m) + (has2 ? __expf(acc1 - m) : 0.f);
#pragma unroll
        for (int o = 16; o; o >>= 1)
            s += __shfl_xor_sync(0xffffffffu, s, o);

        float lse = m + __logf(s);
        out[n * NC + lane] = acc0 - lse;
        if (has2) out[n * NC + lane + 32] = acc1 - lse;
        __syncwarp();
    }
}

// ---------------------------------------------------------------------------
// Launch: zero+probe -> build (once) -> fused layer x2 -> classifier.
// ---------------------------------------------------------------------------
extern "C" void kernel_launch(void* const* d_in, const int* in_sizes, int n_in,
                              void* d_out, int out_size) {
    const float* x  = (const float*)d_in[0];
    const void*  ei = d_in[1];
    const float* W1 = (const float*)d_in[2];
    const float* b1 = (const float*)d_in[3];
    const float* W2 = (const float*)d_in[4];
    const float* b2 = (const float*)d_in[5];
    const float* Wf = (const float*)d_in[6];
    const float* bf = (const float*)d_in[7];
    float* out = (float*)d_out;

    const int zero_blocks  = (N_NODES + 255) / 256;
    const int build_blocks = (N_EDGES + 255) / 256;
    const int fused_blocks = 304;     // 2 resident blocks/SM x 152 SMs
    const int cls_blocks   = 1184;

    zero_probe_kernel<<<zero_blocks, 256>>>((const int*)ei);
    build_kernel<<<build_blocks, 256>>>(ei);

    fused_layer_kernel<<<fused_blocks, 256>>>((const float4*)x, W1, b1, 1);
    fused_layer_kernel<<<fused_blocks, 256>>>((const float4*)x, W2, b2, 0);

    classifier_kernel<<<cls_blocks, 256>>>(Wf, bf, out);
}

// round 17
// speedup vs baseline: 1.1001x; 1.1001x over previous
#include <cuda_runtime.h>
#include <math.h>

// Problem constants (fixed by the dataset)
#define N_NODES 100000
#define N_EDGES 1600000
#define NF      64
#define NC      40
#define CAP     64      // per-node slots; max degree ~38 (1.6M-into-100K multinomial)
#define GRP     16      // nodes per MLP iteration (100000 % 16 == 0)

// Scratch: __device__ globals. float4-typed arrays are 16B-aligned.
// Referenced ONLY from device code (host-side &global is the R10 bug).
__device__ float4 g_agg4[N_NODES * NF / 4];   // (h + sum msgs) per node
__device__ float4 g_h1_4[N_NODES * NF / 4];   // hidden after layer 1
__device__ float4 g_h2_4[N_NODES * NF / 4];   // hidden after layer 2
__device__ int    g_cnt [N_NODES];            // per-dst message count
__device__ int    g_slot[N_NODES * CAP];      // per-dst source-node lists
__device__ int    g_ei_is64;                  // 1 if edge_index is int64

// ---------------------------------------------------------------------------
// Zero per-node counters; thread 0 probes edge_index dtype (int64 ids < 2^31
// -> every odd 32-bit word zero; random int32 ids in [0,1e5) never are).
// ---------------------------------------------------------------------------
__global__ void zero_probe_kernel(const int* __restrict__ ei32) {
    int i = blockIdx.x * blockDim.x + threadIdx.x;
    if (i < N_NODES) g_cnt[i] = 0;
    if (i == 0) {
        int allzero = 1;
        for (int k = 1; k < 128; k += 2)
            if (ei32[k] != 0) { allzero = 0; break; }
        g_ei_is64 = allzero;
    }
}

// ---------------------------------------------------------------------------
// Build per-dst source lists ONCE (used by both layers). Ticketed atomicAdd
// into distinct addresses (~16 avg contention). Slot order is race-dependent;
// summation is commutative, verified by tolerance.
// ---------------------------------------------------------------------------
__global__ void build_kernel(const void* __restrict__ ei_raw) {
    int e = blockIdx.x * blockDim.x + threadIdx.x;
    if (e >= N_EDGES) return;
    int src, dst;
    if (g_ei_is64) {
        const long long* ei = (const long long*)ei_raw;
        src = (int)ei[e];
        dst = (int)ei[N_EDGES + e];
    } else {
        const int* ei = (const int*)ei_raw;
        src = ei[e];
        dst = ei[N_EDGES + e];
    }
    if ((unsigned)src >= N_NODES || (unsigned)dst >= N_NODES) return;
    int t = atomicAdd(&g_cnt[dst], 1);
    if (t < CAP) g_slot[dst * CAP + t] = src;
}

// ---------------------------------------------------------------------------
// Gather-side aggregation, NO atomics: g_agg[n] = h[n] + sum_{s in list(n)} h[s].
// 16 threads per node (one float4 chunk each), coalesced 256B row gathers.
// Degree loop unrolled x4 -> 4 outstanding gathers hide L2 latency.
// At the LTS byte roofline (~410MB gather / 6300 B/cyc); leave as-is.
// layer1 != 0 reads x, else reads g_h1.
// ---------------------------------------------------------------------------
__global__ void aggregate_kernel(const float4* __restrict__ xin, int layer1) {
    int idx = blockIdx.x * blockDim.x + threadIdx.x;
    if (idx >= N_NODES * 16) return;
    int n = idx >> 4;
    int c = idx & 15;

    const float4* h4 = layer1 ? xin : g_h1_4;
    float4 acc = h4[n * 16 + c];               // self-term (GIN eps=0)
    int deg = g_cnt[n];
    if (deg > CAP) deg = CAP;
    const int* sl = g_slot + n * CAP;

    int d = 0;
    for (; d + 4 <= deg; d += 4) {
        int s0 = sl[d], s1 = sl[d + 1], s2 = sl[d + 2], s3 = sl[d + 3];
        float4 v0 = h4[s0 * 16 + c];
        float4 v1 = h4[s1 * 16 + c];
        float4 v2 = h4[s2 * 16 + c];
        float4 v3 = h4[s3 * 16 + c];
        acc.x += (v0.x + v1.x) + (v2.x + v3.x);
        acc.y += (v0.y + v1.y) + (v2.y + v3.y);
        acc.z += (v0.z + v1.z) + (v2.z + v3.z);
        acc.w += (v0.w + v1.w) + (v2.w + v3.w);
    }
    for (; d < deg; d++) {
        float4 v = h4[sl[d] * 16 + c];
        acc.x += v.x; acc.y += v.y; acc.z += v.z; acc.w += v.w;
    }
    g_agg4[n * 16 + c] = acc;
}

// ---------------------------------------------------------------------------
// GIN MLP: out = relu(g_agg @ W + b). 16 nodes per iteration, double-buffered
// smem, ONE barrier per iteration (256 FMAs/thread amortize it; R15 had only
// 64 FMAs across 2 barriers). Per iter per thread: 4 coalesced LDG prefetches
// (issued right after the barrier, latency hidden by compute), 4 STS, then
// 4 nodes x (16 LDS.128 broadcast + 64 FMA on 4 accumulator chains).
// W column in registers (reused across all nodes). 3 blocks/SM.
// layer1 != 0: write g_h1; else write g_h2.
// ---------------------------------------------------------------------------
__global__ void __launch_bounds__(256, 3)
gin_mlp_kernel(const float* __restrict__ W,
               const float* __restrict__ b,
               int layer1) {
    __shared__ __align__(16) float tin[2][GRP * NF];   // 2 x 4KB
    const float* agg = (const float*)g_agg4;
    float*       out = layer1 ? (float*)g_h1_4 : (float*)g_h2_4;

    int t  = threadIdx.x;     // 0..255
    int nl = t >> 6;          // node base 0..3 (computes nl, nl+4, nl+8, nl+12)
    int j  = t & 63;          // output column

    float w[NF];
#pragma unroll
    for (int k = 0; k < NF; k++) w[k] = W[k * NF + j];
    float bias = b[j];

    const int ngroups = N_NODES / GRP;        // 6250
    int g = blockIdx.x;
    float r0 = 0.f, r1 = 0.f, r2 = 0.f, r3 = 0.f;
    if (g < ngroups) {                        // prologue load (coalesced)
        const float* base = agg + g * (GRP * NF);
        r0 = base[t]; r1 = base[t + 256]; r2 = base[t + 512]; r3 = base[t + 768];
    }
    int p = 0;

    for (; g < ngroups; g += gridDim.x) {
        tin[p][t]       = r0;                 // publish group g
        tin[p][t + 256] = r1;
        tin[p][t + 512] = r2;
        tin[p][t + 768] = r3;
        __syncthreads();

        int gn = g + gridDim.x;               // prefetch next group (no await)
        if (gn < ngroups) {
            const float* base = agg + gn * (GRP * NF);
            r0 = base[t]; r1 = base[t + 256]; r2 = base[t + 512]; r3 = base[t + 768];
        }

#pragma unroll
        for (int m = 0; m < 4; m++) {
            const float* row = &tin[p][(nl + 4 * m) * NF];
            float a0 = bias, a1 = 0.f, a2 = 0.f, a3 = 0.f;
#pragma unroll
            for (int k = 0; k < NF / 4; k++) {
                float4 v = *(const float4*)(row + 4 * k);
                a0 = fmaf(v.x, w[4 * k],     a0);
                a1 = fmaf(v.y, w[4 * k + 1], a1);
                a2 = fmaf(v.z, w[4 * k + 2], a2);
                a3 = fmaf(v.w, w[4 * k + 3], a3);
            }
            out[(g * GRP + nl + 4 * m) * NF + j] = fmaxf((a0 + a1) + (a2 + a3), 0.f);
        }
        p ^= 1;
    }
}

// ---------------------------------------------------------------------------
// Classifier: logits = h2 @ Wf + bf (64 -> 40), per-row log_softmax.
// One warp per node; Wf/bf in smem; LDS.128 h-row; prefetch; shuffles; MUFU.
// Lane j owns classes j and j+32 (latter for j < 8).
// ---------------------------------------------------------------------------
__global__ void classifier_kernel(const float* __restrict__ Wf,
                                  const float* __restrict__ bf,
                                  float* __restrict__ out) {
    __shared__ float Wfs[NF * NC];
    __shared__ float bfs[NC];
    __shared__ __align__(16) float hrow[8][NF];

    const float* h2 = (const float*)g_h2_4;
    int t = threadIdx.x;
    for (int i = t; i < NF * NC; i += blockDim.x) Wfs[i] = Wf[i];
    if (t < NC) bfs[t] = bf[t];
    __syncthreads();

    int w    = t >> 5;
    int lane = t & 31;
    int warps_total = gridDim.x * (blockDim.x >> 5);
    int wg   = blockIdx.x * (blockDim.x >> 5) + w;
    bool has2 = lane < (NC - 32);

    int n = wg;
    float p0 = 0.f, p1 = 0.f;
    if (n < N_NODES) { p0 = h2[n * NF + lane]; p1 = h2[n * NF + 32 + lane]; }

    for (; n < N_NODES; n += warps_total) {
        hrow[w][lane]      = p0;
        hrow[w][lane + 32] = p1;
        __syncwarp();

        int nn = n + warps_total;
        if (nn < N_NODES) {
            p0 = h2[nn * NF + lane];
            p1 = h2[nn * NF + 32 + lane];
        }

        float acc0 = bfs[lane];
        float acc1 = has2 ? bfs[lane + 32] : 0.f;
#pragma unroll
        for (int k = 0; k < NF / 4; k++) {
            float4 hv = *(const float4*)&hrow[w][4 * k];
            acc0 = fmaf(hv.x, Wfs[(4 * k)     * NC + lane], acc0);
            acc0 = fmaf(hv.y, Wfs[(4 * k + 1) * NC + lane], acc0);
            acc0 = fmaf(hv.z, Wfs[(4 * k + 2) * NC + lane], acc0);
            acc0 = fmaf(hv.w, Wfs[(4 * k + 3) * NC + lane], acc0);
            if (has2) {
                acc1 = fmaf(hv.x, Wfs[(4 * k)     * NC + lane + 32], acc1);
                acc1 = fmaf(hv.y, Wfs[(4 * k + 1) * NC + lane + 32], acc1);
                acc1 = fmaf(hv.z, Wfs[(4 * k + 2) * NC + lane + 32], acc1);
                acc1 = fmaf(hv.w, Wfs[(4 * k + 3) * NC + lane + 32], acc1);
            }
        }

        float m = has2 ? fmaxf(acc0, acc1) : acc0;
#pragma unroll
        for (int o = 16; o; o >>= 1)
            m = fmaxf(m, __shfl_xor_sync(0xffffffffu, m, o));

        float s = __expf(acc0 - m) + (has2 ? __expf(acc1 - m) : 0.f);
#pragma unroll
        for (int o = 16; o; o >>= 1)
            s += __shfl_xor_sync(0xffffffffu, s, o);

        float lse = m + __logf(s);
        out[n * NC + lane] = acc0 - lse;
        if (has2) out[n * NC + lane + 32] = acc1 - lse;
        __syncwarp();
    }
}

// ---------------------------------------------------------------------------
// Launch: zero+probe -> build (once) -> [aggregate -> mlp] x2 -> classifier.
// ---------------------------------------------------------------------------
extern "C" void kernel_launch(void* const* d_in, const int* in_sizes, int n_in,
                              void* d_out, int out_size) {
    const float* x  = (const float*)d_in[0];
    const void*  ei = d_in[1];
    const float* W1 = (const float*)d_in[2];
    const float* b1 = (const float*)d_in[3];
    const float* W2 = (const float*)d_in[4];
    const float* b2 = (const float*)d_in[5];
    const float* Wf = (const float*)d_in[6];
    const float* bf = (const float*)d_in[7];
    float* out = (float*)d_out;

    const int zero_blocks  = (N_NODES + 255) / 256;
    const int build_blocks = (N_EDGES + 255) / 256;
    const int agg_blocks   = (N_NODES * 16 + 255) / 256;
    const int mlp_blocks   = 456;     // 3 blocks/SM x 152 SMs
    const int cls_blocks   = 1184;

    zero_probe_kernel<<<zero_blocks, 256>>>((const int*)ei);
    build_kernel<<<build_blocks, 256>>>(ei);

    // Layer 1: agg = x + sum_msgs(x) -> h1
    aggregate_kernel<<<agg_blocks, 256>>>((const float4*)x, 1);
    gin_mlp_kernel<<<mlp_blocks, 256>>>(W1, b1, 1);

    // Layer 2: agg = h1 + sum_msgs(h1) -> h2
    aggregate_kernel<<<agg_blocks, 256>>>((const float4*)x, 0);
    gin_mlp_kernel<<<mlp_blocks, 256>>>(W2, b2, 0);

    // Classifier + log_softmax
    classifier_kernel<<<cls_blocks, 256>>>(Wf, bf, out);
}